// round 1
// baseline (speedup 1.0000x reference)
#include <cuda_runtime.h>
#include <math.h>

#define TB 2048
#define CB 1024
#define BSZ 2
#define HH 16
#define DD 64
#define NCH 32   // chunks of 64 along T
#define BHN 32   // BSZ*HH

// ---------------- scratch (static device allocations; no cudaMalloc) ----------
__device__ float g_qkv[(size_t)BSZ * TB * 3 * CB];        // 50.3 MB
__device__ float g_kv [(size_t)BHN * NCH * DD * DD];      // 16.8 MB (per-chunk K^T V, then excl. prefix)
__device__ float g_kz [(size_t)BHN * NCH * DD];           // per-chunk k sums, then excl. prefix
__device__ float g_y  [(size_t)BSZ * TB * CB];            // 16.8 MB attention output

__device__ __forceinline__ float phi(float x) {           // elu(x)+1
    return x > 0.f ? x + 1.f : expf(x);
}

// ---------------- SGEMM: C(MxN) = A(MxK) @ B(KxN), 128x128 block, 8x8 micro ---
__device__ __forceinline__ void sgemm_body(const float* __restrict__ A,
                                           const float* __restrict__ B,
                                           float* __restrict__ C,
                                           int N, int K) {
    __shared__ float As[16][132];   // transposed A tile, padded
    __shared__ float Bs[16][128];
    int tid = threadIdx.x;
    int bn = blockIdx.x * 128;
    int bm = blockIdx.y * 128;
    int tx = tid & 15, ty = tid >> 4;
    int arow = tid >> 2;            // 0..63
    int acol = (tid & 3) << 2;      // 0,4,8,12
    int brow = tid >> 5;            // 0..7
    int bcol = (tid & 31) << 2;     // 0..124

    float acc[8][8];
#pragma unroll
    for (int i = 0; i < 8; i++)
#pragma unroll
        for (int j = 0; j < 8; j++) acc[i][j] = 0.f;

    const float* Ap0 = A + (size_t)(bm + arow) * K + acol;
    const float* Ap1 = A + (size_t)(bm + arow + 64) * K + acol;
    const float* Bp0 = B + (size_t)brow * N + bn + bcol;
    const float* Bp1 = B + (size_t)(brow + 8) * N + bn + bcol;

    for (int k0 = 0; k0 < K; k0 += 16) {
        float4 a0 = *(const float4*)(Ap0 + k0);
        float4 a1 = *(const float4*)(Ap1 + k0);
        float4 b0 = *(const float4*)(Bp0 + (size_t)k0 * N);
        float4 b1 = *(const float4*)(Bp1 + (size_t)k0 * N);
        __syncthreads();
        As[acol + 0][arow] = a0.x; As[acol + 1][arow] = a0.y;
        As[acol + 2][arow] = a0.z; As[acol + 3][arow] = a0.w;
        As[acol + 0][arow + 64] = a1.x; As[acol + 1][arow + 64] = a1.y;
        As[acol + 2][arow + 64] = a1.z; As[acol + 3][arow + 64] = a1.w;
        *(float4*)&Bs[brow][bcol] = b0;
        *(float4*)&Bs[brow + 8][bcol] = b1;
        __syncthreads();
#pragma unroll
        for (int kk = 0; kk < 16; kk++) {
            float ra[8], rb[8];
#pragma unroll
            for (int i = 0; i < 8; i++) ra[i] = As[kk][ty * 8 + i];
#pragma unroll
            for (int j = 0; j < 8; j++) rb[j] = Bs[kk][tx * 8 + j];
#pragma unroll
            for (int i = 0; i < 8; i++)
#pragma unroll
                for (int j = 0; j < 8; j++)
                    acc[i][j] += ra[i] * rb[j];
        }
    }
#pragma unroll
    for (int i = 0; i < 8; i++) {
        float* crow = C + (size_t)(bm + ty * 8 + i) * N + bn + tx * 8;
        *(float4*)crow       = make_float4(acc[i][0], acc[i][1], acc[i][2], acc[i][3]);
        *(float4*)(crow + 4) = make_float4(acc[i][4], acc[i][5], acc[i][6], acc[i][7]);
    }
}

__global__ __launch_bounds__(256) void gemm_qkv_kernel(const float* __restrict__ x,
                                                       const float* __restrict__ w) {
    sgemm_body(x, w, g_qkv, 3 * CB, CB);
}
__global__ __launch_bounds__(256) void gemm_proj_kernel(const float* __restrict__ w,
                                                        float* __restrict__ out) {
    sgemm_body(g_y, w, out, CB, CB);
}

// ---------------- Phase A: per-chunk KV = phi(K)^T V  and  kz = sum phi(k) ----
__global__ __launch_bounds__(256) void chunk_kv_kernel() {
    int bid = blockIdx.x;
    int bh = bid >> 5, c = bid & 31;
    int b = bh >> 4, h = bh & 15;
    int tid = threadIdx.x;
    __shared__ float sK[64][65];
    __shared__ float sV[64][65];

    const float* base = g_qkv + (size_t)(b * TB + c * 64) * (3 * CB) + h * 64;
#pragma unroll
    for (int it = 0; it < 4; it++) {
        int idx = tid + it * 256;            // 0..1023
        int r = idx >> 4;
        int c4 = (idx & 15) << 2;
        float4 kk = *(const float4*)(base + (size_t)r * (3 * CB) + CB + c4);
        float4 vv = *(const float4*)(base + (size_t)r * (3 * CB) + 2 * CB + c4);
        sK[r][c4 + 0] = phi(kk.x); sK[r][c4 + 1] = phi(kk.y);
        sK[r][c4 + 2] = phi(kk.z); sK[r][c4 + 3] = phi(kk.w);
        sV[r][c4 + 0] = vv.x; sV[r][c4 + 1] = vv.y;
        sV[r][c4 + 2] = vv.z; sV[r][c4 + 3] = vv.w;
    }
    __syncthreads();

    int ii0 = (tid >> 4) << 2;
    int jj0 = (tid & 15) << 2;
    float a[4][4];
#pragma unroll
    for (int i = 0; i < 4; i++)
#pragma unroll
        for (int j = 0; j < 4; j++) a[i][j] = 0.f;

#pragma unroll 4
    for (int t = 0; t < 64; t++) {
        float kr[4], vr[4];
#pragma unroll
        for (int i = 0; i < 4; i++) kr[i] = sK[t][ii0 + i];
#pragma unroll
        for (int j = 0; j < 4; j++) vr[j] = sV[t][jj0 + j];
#pragma unroll
        for (int i = 0; i < 4; i++)
#pragma unroll
            for (int j = 0; j < 4; j++)
                a[i][j] += kr[i] * vr[j];
    }

    float* kvout = g_kv + (size_t)(bh * NCH + c) * (DD * DD);
#pragma unroll
    for (int i = 0; i < 4; i++)
        *(float4*)&kvout[(ii0 + i) * 64 + jj0] =
            make_float4(a[i][0], a[i][1], a[i][2], a[i][3]);

    if (tid < 64) {
        float s = 0.f;
#pragma unroll 8
        for (int t = 0; t < 64; t++) s += sK[t][tid];
        g_kz[(size_t)(bh * NCH + c) * 64 + tid] = s;
    }
}

// ---------------- Phase B: in-place exclusive prefix over chunks --------------
__global__ void scan_kv_kernel() {
    int e = blockIdx.x * 256 + threadIdx.x;     // BHN*4096 = 131072 total
    int bh = e >> 12, ij = e & 4095;
    float* p = g_kv + (size_t)bh * NCH * 4096 + ij;
    float run = 0.f;
    for (int c = 0; c < NCH; c++) {
        float v = p[(size_t)c * 4096];
        p[(size_t)c * 4096] = run;
        run += v;
    }
}
__global__ void scan_kz_kernel() {
    int e = blockIdx.x * 256 + threadIdx.x;     // BHN*64 = 2048 total
    int bh = e >> 6, i = e & 63;
    float* p = g_kz + (size_t)bh * NCH * 64 + i;
    float run = 0.f;
    for (int c = 0; c < NCH; c++) {
        float v = p[(size_t)c * 64];
        p[(size_t)c * 64] = run;
        run += v;
    }
}

// ---------------- Phase C: per-chunk output ----------------------------------
// y_t = (Q S + mask(QK^T) V) / (Q.z + rowsum(mask(QK^T)) + eps)
__global__ __launch_bounds__(256) void attn_out_kernel() {
    int bid = blockIdx.x;
    int bh = bid >> 5, cidx = bid & 31;
    int b = bh >> 4, h = bh & 15;
    int tid = threadIdx.x;
    int t = tid >> 2;          // row 0..63
    int cc = tid & 3;          // column-group

    __shared__ float sQ[64][65];
    __shared__ float sK[64][65];
    __shared__ float sS[16][64];
    __shared__ float sV[16][64];
    __shared__ float sA[64][17];
    __shared__ float sz[64];

    const float* base = g_qkv + (size_t)(b * TB + cidx * 64) * (3 * CB) + h * 64;
#pragma unroll
    for (int it = 0; it < 4; it++) {
        int idx = tid + it * 256;
        int r = idx >> 4;
        int c4 = (idx & 15) << 2;
        float4 q4 = *(const float4*)(base + (size_t)r * (3 * CB) + c4);
        float4 k4 = *(const float4*)(base + (size_t)r * (3 * CB) + CB + c4);
        sQ[r][c4 + 0] = phi(q4.x); sQ[r][c4 + 1] = phi(q4.y);
        sQ[r][c4 + 2] = phi(q4.z); sQ[r][c4 + 3] = phi(q4.w);
        sK[r][c4 + 0] = phi(k4.x); sK[r][c4 + 1] = phi(k4.y);
        sK[r][c4 + 2] = phi(k4.z); sK[r][c4 + 3] = phi(k4.w);
    }
    if (tid < 64) sz[tid] = g_kz[(size_t)(bh * NCH + cidx) * 64 + tid];
    __syncthreads();

    float acc[16];
#pragma unroll
    for (int dd = 0; dd < 16; dd++) acc[dd] = 0.f;
    float den = 0.f;
#pragma unroll 8
    for (int i = 0; i < 64; i++) den += sQ[t][i] * sz[i];

    // inter-chunk: Q @ S  (S streamed in 16-row slices)
    const float* Sg = g_kv + (size_t)(bh * NCH + cidx) * 4096;
    for (int i0 = 0; i0 < 64; i0 += 16) {
        {
            int r = tid >> 4, c4 = (tid & 15) << 2;
            *(float4*)&sS[r][c4] = *(const float4*)&Sg[(i0 + r) * 64 + c4];
        }
        __syncthreads();
#pragma unroll
        for (int i = 0; i < 16; i++) {
            float qv = sQ[t][i0 + i];
#pragma unroll
            for (int dd = 0; dd < 16; dd++)
                acc[dd] += qv * sS[i][cc + 4 * dd];
        }
        __syncthreads();
    }

    // intra-chunk: masked QK^T, then @V, V streamed in 16-row slices
    for (int s0 = 0; s0 < 64; s0 += 16) {
        {
            int r = tid >> 4, c4 = (tid & 15) << 2;
            *(float4*)&sV[r][c4] =
                *(const float4*)(base + (size_t)(s0 + r) * (3 * CB) + 2 * CB + c4);
        }
#pragma unroll
        for (int u = 0; u < 4; u++) {
            int ss = cc * 4 + u;
            int s = s0 + ss;
            float a = 0.f;
            if (s <= t) {
#pragma unroll 8
                for (int i = 0; i < 64; i++) a += sQ[t][i] * sK[s][i];
            }
            sA[t][ss] = a;
        }
        __syncthreads();
#pragma unroll
        for (int ss = 0; ss < 16; ss++) {
            float a = sA[t][ss];
            den += a;
#pragma unroll
            for (int dd = 0; dd < 16; dd++)
                acc[dd] += a * sV[ss][cc + 4 * dd];
        }
        __syncthreads();
    }

    float inv = 1.f / (den + 1e-6f);
    float* yout = g_y + (size_t)(b * TB + cidx * 64 + t) * CB + h * 64;
#pragma unroll
    for (int dd = 0; dd < 16; dd++)
        yout[cc + 4 * dd] = acc[dd] * inv;
}

// ---------------- launch ------------------------------------------------------
extern "C" void kernel_launch(void* const* d_in, const int* in_sizes, int n_in,
                              void* d_out, int out_size) {
    const float* x      = (const float*)d_in[0];
    const float* w_attn = (const float*)d_in[1];
    const float* w_proj = (const float*)d_in[2];
    float* out = (float*)d_out;

    dim3 g1(3 * CB / 128, BSZ * TB / 128);   // (24, 32)
    gemm_qkv_kernel<<<g1, 256>>>(x, w_attn);

    chunk_kv_kernel<<<BHN * NCH, 256>>>();
    scan_kv_kernel<<<(BHN * 4096) / 256, 256>>>();
    scan_kz_kernel<<<(BHN * 64) / 256, 256>>>();
    attn_out_kernel<<<BHN * NCH, 256>>>();

    dim3 g2(CB / 128, BSZ * TB / 128);       // (8, 32)
    gemm_proj_kernel<<<g2, 256>>>(w_proj, out);
}

// round 3
// speedup vs baseline: 2.4675x; 2.4675x over previous
#include <cuda_runtime.h>
#include <math.h>
#include <stdint.h>

#define TB 2048
#define CB 1024
#define BSZ 2
#define HH 16
#define DD 64
#define NCH 32   // chunks of 64 along T
#define BHN 32   // BSZ*HH

// ---------------- scratch (static device allocations; no cudaMalloc) ----------
__device__ float g_qkv[(size_t)BSZ * TB * 3 * CB];        // 50.3 MB
__device__ float g_kv [(size_t)BHN * NCH * DD * DD];      // 16.8 MB
__device__ float g_kz [(size_t)BHN * NCH * DD];
__device__ float g_y  [(size_t)BSZ * TB * CB];            // 16.8 MB

__device__ __forceinline__ float phi(float x) {           // elu(x)+1
    return x > 0.f ? x + 1.f : expf(x);
}

__device__ __forceinline__ uint32_t f2tf32(float x) {
    uint32_t r;
    asm("cvt.rna.tf32.f32 %0, %1;" : "=r"(r) : "f"(x));
    return r;
}

// ---------------- TF32 tensor-core GEMM: C(MxN)=A(MxK)@B(KxN) ------------------
// 128x128 block tile, 256 threads (8 warps, 2x4), warp tile 64x32,
// K-step 32, mma.sync.m16n8k8.tf32. Conflict-free smem strides.
__device__ __forceinline__ void tgemm_body(const float* __restrict__ A,
                                           const float* __restrict__ B,
                                           float* __restrict__ C,
                                           int N, int K) {
    __shared__ uint32_t As[128][36];   // bank = (4*row+col)%32 -> conflict free
    __shared__ uint32_t Bs[32][136];   // bank = (8*k+n)%32   -> conflict free

    int tid  = threadIdx.x;
    int lane = tid & 31;
    int warp = tid >> 5;
    int wm = (warp >> 2) * 64;         // 0 / 64
    int wn = (warp & 3) * 32;          // 0,32,64,96
    int bm = blockIdx.y * 128;
    int bn = blockIdx.x * 128;

    float acc[4][4][4];
#pragma unroll
    for (int mi = 0; mi < 4; mi++)
#pragma unroll
        for (int ni = 0; ni < 4; ni++)
#pragma unroll
            for (int r = 0; r < 4; r++) acc[mi][ni][r] = 0.f;

    // A loader: f = tid + i*256 (0..1023): row=f>>3 (128), col4=(f&7)*4 (32 cols)
    // B loader: row=f>>5 (32), col4=(f&31)*4 (128 cols)
    int ar = tid >> 3, ac = (tid & 7) << 2;
    int br = tid >> 5, bc = (tid & 31) << 2;

    const int lq = lane >> 2;   // quad row 0..7
    const int lr = lane & 3;    // 0..3

    for (int k0 = 0; k0 < K; k0 += 32) {
        float4 a[4], b[4];
#pragma unroll
        for (int i = 0; i < 4; i++) {
            int rr = ar + i * 32;
            a[i] = *(const float4*)(A + (size_t)(bm + rr) * K + k0 + ac);
        }
#pragma unroll
        for (int i = 0; i < 4; i++) {
            int rr = br + i * 8;
            b[i] = *(const float4*)(B + (size_t)(k0 + rr) * N + bn + bc);
        }
        __syncthreads();
#pragma unroll
        for (int i = 0; i < 4; i++) {
            int rr = ar + i * 32;
            As[rr][ac + 0] = f2tf32(a[i].x); As[rr][ac + 1] = f2tf32(a[i].y);
            As[rr][ac + 2] = f2tf32(a[i].z); As[rr][ac + 3] = f2tf32(a[i].w);
        }
#pragma unroll
        for (int i = 0; i < 4; i++) {
            int rr = br + i * 8;
            Bs[rr][bc + 0] = f2tf32(b[i].x); Bs[rr][bc + 1] = f2tf32(b[i].y);
            Bs[rr][bc + 2] = f2tf32(b[i].z); Bs[rr][bc + 3] = f2tf32(b[i].w);
        }
        __syncthreads();

#pragma unroll
        for (int ks = 0; ks < 4; ks++) {
            int kb = ks * 8;
            uint32_t af[4][4], bf[4][2];
#pragma unroll
            for (int mi = 0; mi < 4; mi++) {
                int r0 = wm + mi * 16 + lq;
                af[mi][0] = As[r0    ][kb + lr];
                af[mi][1] = As[r0 + 8][kb + lr];
                af[mi][2] = As[r0    ][kb + 4 + lr];
                af[mi][3] = As[r0 + 8][kb + 4 + lr];
            }
#pragma unroll
            for (int ni = 0; ni < 4; ni++) {
                int c0 = wn + ni * 8 + lq;
                bf[ni][0] = Bs[kb + lr    ][c0];
                bf[ni][1] = Bs[kb + 4 + lr][c0];
            }
#pragma unroll
            for (int mi = 0; mi < 4; mi++)
#pragma unroll
                for (int ni = 0; ni < 4; ni++) {
                    asm volatile(
                        "mma.sync.aligned.m16n8k8.row.col.f32.tf32.tf32.f32 "
                        "{%0,%1,%2,%3}, {%4,%5,%6,%7}, {%8,%9}, {%0,%1,%2,%3};"
                        : "+f"(acc[mi][ni][0]), "+f"(acc[mi][ni][1]),
                          "+f"(acc[mi][ni][2]), "+f"(acc[mi][ni][3])
                        : "r"(af[mi][0]), "r"(af[mi][1]), "r"(af[mi][2]), "r"(af[mi][3]),
                          "r"(bf[ni][0]), "r"(bf[ni][1]));
                }
        }
    }

#pragma unroll
    for (int mi = 0; mi < 4; mi++)
#pragma unroll
        for (int ni = 0; ni < 4; ni++) {
            int r = bm + wm + mi * 16 + lq;
            int c = bn + wn + ni * 8 + lr * 2;
            *(float2*)(C + (size_t)r * N + c) =
                make_float2(acc[mi][ni][0], acc[mi][ni][1]);
            *(float2*)(C + (size_t)(r + 8) * N + c) =
                make_float2(acc[mi][ni][2], acc[mi][ni][3]);
        }
}

__global__ __launch_bounds__(256) void gemm_qkv_kernel(const float* __restrict__ x,
                                                       const float* __restrict__ w) {
    tgemm_body(x, w, g_qkv, 3 * CB, CB);
}
__global__ __launch_bounds__(256) void gemm_proj_kernel(const float* __restrict__ w,
                                                        float* __restrict__ out) {
    tgemm_body(g_y, w, out, CB, CB);
}

// ---------------- Phase A: per-chunk KV = phi(K)^T V  and  kz = sum phi(k) ----
__global__ __launch_bounds__(256) void chunk_kv_kernel() {
    int bid = blockIdx.x;
    int bh = bid >> 5, c = bid & 31;
    int b = bh >> 4, h = bh & 15;
    int tid = threadIdx.x;
    __shared__ float sK[64][65];
    __shared__ float sV[64][65];

    const float* base = g_qkv + (size_t)(b * TB + c * 64) * (3 * CB) + h * 64;
#pragma unroll
    for (int it = 0; it < 4; it++) {
        int idx = tid + it * 256;            // 0..1023
        int r = idx >> 4;
        int c4 = (idx & 15) << 2;
        float4 kk = *(const float4*)(base + (size_t)r * (3 * CB) + CB + c4);
        float4 vv = *(const float4*)(base + (size_t)r * (3 * CB) + 2 * CB + c4);
        sK[r][c4 + 0] = phi(kk.x); sK[r][c4 + 1] = phi(kk.y);
        sK[r][c4 + 2] = phi(kk.z); sK[r][c4 + 3] = phi(kk.w);
        sV[r][c4 + 0] = vv.x; sV[r][c4 + 1] = vv.y;
        sV[r][c4 + 2] = vv.z; sV[r][c4 + 3] = vv.w;
    }
    __syncthreads();

    int ii0 = (tid >> 4) << 2;
    int jj0 = (tid & 15) << 2;
    float a[4][4];
#pragma unroll
    for (int i = 0; i < 4; i++)
#pragma unroll
        for (int j = 0; j < 4; j++) a[i][j] = 0.f;

#pragma unroll 4
    for (int t = 0; t < 64; t++) {
        float kr[4], vr[4];
#pragma unroll
        for (int i = 0; i < 4; i++) kr[i] = sK[t][ii0 + i];
#pragma unroll
        for (int j = 0; j < 4; j++) vr[j] = sV[t][jj0 + j];
#pragma unroll
        for (int i = 0; i < 4; i++)
#pragma unroll
            for (int j = 0; j < 4; j++)
                a[i][j] += kr[i] * vr[j];
    }

    float* kvout = g_kv + (size_t)(bh * NCH + c) * (DD * DD);
#pragma unroll
    for (int i = 0; i < 4; i++)
        *(float4*)&kvout[(ii0 + i) * 64 + jj0] =
            make_float4(a[i][0], a[i][1], a[i][2], a[i][3]);

    if (tid < 64) {
        float s = 0.f;
#pragma unroll 8
        for (int t = 0; t < 64; t++) s += sK[t][tid];
        g_kz[(size_t)(bh * NCH + c) * 64 + tid] = s;
    }
}

// ---------------- Phase B: in-place exclusive prefix over chunks --------------
__global__ void scan_kv_kernel() {
    int e = blockIdx.x * 256 + threadIdx.x;     // BHN*4096 = 131072 total
    int bh = e >> 12, ij = e & 4095;
    float* p = g_kv + (size_t)bh * NCH * 4096 + ij;
    float run = 0.f;
    for (int c = 0; c < NCH; c++) {
        float v = p[(size_t)c * 4096];
        p[(size_t)c * 4096] = run;
        run += v;
    }
}
__global__ void scan_kz_kernel() {
    int e = blockIdx.x * 256 + threadIdx.x;     // BHN*64 = 2048 total
    int bh = e >> 6, i = e & 63;
    float* p = g_kz + (size_t)bh * NCH * 64 + i;
    float run = 0.f;
    for (int c = 0; c < NCH; c++) {
        float v = p[(size_t)c * 64];
        p[(size_t)c * 64] = run;
        run += v;
    }
}

// ---------------- Phase C: per-chunk output ----------------------------------
__global__ __launch_bounds__(256) void attn_out_kernel() {
    int bid = blockIdx.x;
    int bh = bid >> 5, cidx = bid & 31;
    int b = bh >> 4, h = bh & 15;
    int tid = threadIdx.x;
    int t = tid >> 2;          // row 0..63
    int cc = tid & 3;          // column-group

    __shared__ float sQ[64][65];
    __shared__ float sK[64][65];
    __shared__ float sS[16][64];
    __shared__ float sV[16][64];
    __shared__ float sA[64][17];
    __shared__ float sz[64];

    const float* base = g_qkv + (size_t)(b * TB + cidx * 64) * (3 * CB) + h * 64;
#pragma unroll
    for (int it = 0; it < 4; it++) {
        int idx = tid + it * 256;
        int r = idx >> 4;
        int c4 = (idx & 15) << 2;
        float4 q4 = *(const float4*)(base + (size_t)r * (3 * CB) + c4);
        float4 k4 = *(const float4*)(base + (size_t)r * (3 * CB) + CB + c4);
        sQ[r][c4 + 0] = phi(q4.x); sQ[r][c4 + 1] = phi(q4.y);
        sQ[r][c4 + 2] = phi(q4.z); sQ[r][c4 + 3] = phi(q4.w);
        sK[r][c4 + 0] = phi(k4.x); sK[r][c4 + 1] = phi(k4.y);
        sK[r][c4 + 2] = phi(k4.z); sK[r][c4 + 3] = phi(k4.w);
    }
    if (tid < 64) sz[tid] = g_kz[(size_t)(bh * NCH + cidx) * 64 + tid];
    __syncthreads();

    float acc[16];
#pragma unroll
    for (int dd = 0; dd < 16; dd++) acc[dd] = 0.f;
    float den = 0.f;
#pragma unroll 8
    for (int i = 0; i < 64; i++) den += sQ[t][i] * sz[i];

    // inter-chunk: Q @ S  (S streamed in 16-row slices)
    const float* Sg = g_kv + (size_t)(bh * NCH + cidx) * 4096;
    for (int i0 = 0; i0 < 64; i0 += 16) {
        {
            int r = tid >> 4, c4 = (tid & 15) << 2;
            *(float4*)&sS[r][c4] = *(const float4*)&Sg[(i0 + r) * 64 + c4];
        }
        __syncthreads();
#pragma unroll
        for (int i = 0; i < 16; i++) {
            float qv = sQ[t][i0 + i];
#pragma unroll
            for (int dd = 0; dd < 16; dd++)
                acc[dd] += qv * sS[i][cc + 4 * dd];
        }
        __syncthreads();
    }

    // intra-chunk: masked QK^T, then @V, V streamed in 16-row slices
    for (int s0 = 0; s0 < 64; s0 += 16) {
        {
            int r = tid >> 4, c4 = (tid & 15) << 2;
            *(float4*)&sV[r][c4] =
                *(const float4*)(base + (size_t)(s0 + r) * (3 * CB) + 2 * CB + c4);
        }
#pragma unroll
        for (int u = 0; u < 4; u++) {
            int ss = cc * 4 + u;
            int s = s0 + ss;
            float a = 0.f;
            if (s <= t) {
#pragma unroll 8
                for (int i = 0; i < 64; i++) a += sQ[t][i] * sK[s][i];
            }
            sA[t][ss] = a;
        }
        __syncthreads();
#pragma unroll
        for (int ss = 0; ss < 16; ss++) {
            float a = sA[t][ss];
            den += a;
#pragma unroll
            for (int dd = 0; dd < 16; dd++)
                acc[dd] += a * sV[ss][cc + 4 * dd];
        }
        __syncthreads();
    }

    float inv = 1.f / (den + 1e-6f);
    float* yout = g_y + (size_t)(b * TB + cidx * 64 + t) * CB + h * 64;
#pragma unroll
    for (int dd = 0; dd < 16; dd++)
        yout[cc + 4 * dd] = acc[dd] * inv;
}

// ---------------- launch ------------------------------------------------------
extern "C" void kernel_launch(void* const* d_in, const int* in_sizes, int n_in,
                              void* d_out, int out_size) {
    const float* x      = (const float*)d_in[0];
    const float* w_attn = (const float*)d_in[1];
    const float* w_proj = (const float*)d_in[2];
    float* out = (float*)d_out;

    dim3 g1(3 * CB / 128, BSZ * TB / 128);   // (24, 32)
    gemm_qkv_kernel<<<g1, 256>>>(x, w_attn);

    chunk_kv_kernel<<<BHN * NCH, 256>>>();
    scan_kv_kernel<<<(BHN * 4096) / 256, 256>>>();
    scan_kz_kernel<<<(BHN * 64) / 256, 256>>>();
    attn_out_kernel<<<BHN * NCH, 256>>>();

    dim3 g2(CB / 128, BSZ * TB / 128);       // (8, 32)
    gemm_proj_kernel<<<g2, 256>>>(w_proj, out);
}